// round 1
// baseline (speedup 1.0000x reference)
#include <cuda_runtime.h>
#include <cuda_bf16.h>
#include <cstdint>

// ---------------- problem constants ----------------
#define B_      16
#define Q_      300
#define DMODEL  256
#define NHEADS  8
#define HD      32
#define NLVL    3
#define NPTS    4
#define LV      8400          // 80*80 + 40*40 + 20*20
#define BQ      (B_*Q_)       // 4800
#define MV      (B_*LV)       // 134400 rows of value
#define MT_PAD  4864          // 38*128, padded rows for final GEMM input

// ---------------- scratch (device globals; zero-initialized) ----------------
__device__ float g_v[MV * DMODEL];        // projected value  (134400 x 256)
__device__ float g_off[BQ * 192];         // offsets          (4800 x 192)
__device__ float g_attn[BQ * 96];         // attn logits      (4800 x 96)
__device__ float g_tmp[MT_PAD * DMODEL];  // sampled heads    (4864 x 256), rows >=4800 stay 0

// ---------------- helpers ----------------
__device__ __forceinline__ float ftf32(float x) {
    uint32_t u;
    asm("cvt.rna.tf32.f32 %0, %1;" : "=r"(u) : "f"(x));
    return __uint_as_float(u);
}

__device__ __forceinline__ void mma8(float& c0, float& c1, float& c2, float& c3,
                                     uint32_t a0, uint32_t a1, uint32_t a2, uint32_t a3,
                                     uint32_t b0, uint32_t b1) {
    asm volatile(
        "mma.sync.aligned.m16n8k8.row.col.f32.tf32.tf32.f32 "
        "{%0,%1,%2,%3}, {%4,%5,%6,%7}, {%8,%9}, {%0,%1,%2,%3};\n"
        : "+f"(c0), "+f"(c1), "+f"(c2), "+f"(c3)
        : "r"(a0), "r"(a1), "r"(a2), "r"(a3), "r"(b0), "r"(b1));
}

// ============================================================================
// tf32 GEMM:  C[M x N] = A[M x 256] * B[256 x N] + bias,  N multiple of 128.
// Block tile 128x128, BK=32, 8 warps of 64x32. grid = (N/128, Mtiles).
// A rows must be readable up to Mtiles*128 (callers pad); stores guarded.
// ============================================================================
__global__ __launch_bounds__(256, 2)
void gemm_tf32(const float* __restrict__ A, const float* __restrict__ Bm,
               const float* __restrict__ bias, float* __restrict__ C,
               int Mstore, int N) {
    __shared__ float As[128 * 36];   // [m][k] stride 36
    __shared__ float Bs[32 * 136];   // [k][n] stride 136

    const int tid  = threadIdx.x;
    const int warp = tid >> 5, lane = tid & 31;
    const int wm = warp >> 2, wn = warp & 3;       // 2 x 4 warp grid
    const int g  = lane >> 2, tg = lane & 3;

    const int n0 = blockIdx.x * 128;
    const int m0 = blockIdx.y * 128;

    const int arow = tid >> 3,  acol = (tid & 7) * 4;   // A: 4 x float4 per thread
    const int brow = tid >> 5,  bcol = (tid & 31) * 4;  // B: 4 x float4 per thread

    float acc[4][4][4];
    #pragma unroll
    for (int i = 0; i < 4; i++)
        #pragma unroll
        for (int j = 0; j < 4; j++)
            #pragma unroll
            for (int k = 0; k < 4; k++) acc[i][j][k] = 0.f;

    for (int kc = 0; kc < 256; kc += 32) {
        // ---- global -> smem (convert to tf32 at store) ----
        #pragma unroll
        for (int i = 0; i < 4; i++) {
            const float4 va = *reinterpret_cast<const float4*>(
                A + (size_t)(m0 + arow + i * 32) * 256 + kc + acol);
            float4 vc;
            vc.x = ftf32(va.x); vc.y = ftf32(va.y); vc.z = ftf32(va.z); vc.w = ftf32(va.w);
            *reinterpret_cast<float4*>(&As[(arow + i * 32) * 36 + acol]) = vc;
        }
        #pragma unroll
        for (int i = 0; i < 4; i++) {
            const float4 vb = *reinterpret_cast<const float4*>(
                Bm + (size_t)(kc + brow + i * 8) * N + n0 + bcol);
            float4 vc;
            vc.x = ftf32(vb.x); vc.y = ftf32(vb.y); vc.z = ftf32(vb.z); vc.w = ftf32(vb.w);
            *reinterpret_cast<float4*>(&Bs[(brow + i * 8) * 136 + bcol]) = vc;
        }
        __syncthreads();

        // ---- 4 k8-steps of mma ----
        #pragma unroll
        for (int k8 = 0; k8 < 4; k8++) {
            const int kb = k8 * 8;
            uint32_t af[4][4], bf[4][2];
            const float* apA = &As[(wm * 64 + g) * 36 + kb + tg];
            #pragma unroll
            for (int mi = 0; mi < 4; mi++) {
                af[mi][0] = __float_as_uint(apA[mi * 576]);          // (g      , tg  )
                af[mi][1] = __float_as_uint(apA[mi * 576 + 288]);    // (g+8    , tg  )
                af[mi][2] = __float_as_uint(apA[mi * 576 + 4]);      // (g      , tg+4)
                af[mi][3] = __float_as_uint(apA[mi * 576 + 292]);    // (g+8    , tg+4)
            }
            const float* bpB = &Bs[(kb + tg) * 136 + wn * 32 + g];
            #pragma unroll
            for (int ni = 0; ni < 4; ni++) {
                bf[ni][0] = __float_as_uint(bpB[ni * 8]);            // (tg  , n)
                bf[ni][1] = __float_as_uint(bpB[544 + ni * 8]);      // (tg+4, n)
            }
            #pragma unroll
            for (int mi = 0; mi < 4; mi++)
                #pragma unroll
                for (int ni = 0; ni < 4; ni++)
                    mma8(acc[mi][ni][0], acc[mi][ni][1], acc[mi][ni][2], acc[mi][ni][3],
                         af[mi][0], af[mi][1], af[mi][2], af[mi][3],
                         bf[ni][0], bf[ni][1]);
        }
        __syncthreads();
    }

    // ---- epilogue: + bias, guarded float2 stores ----
    #pragma unroll
    for (int mi = 0; mi < 4; mi++) {
        const int r0 = m0 + wm * 64 + mi * 16 + g;
        const int r1 = r0 + 8;
        #pragma unroll
        for (int ni = 0; ni < 4; ni++) {
            const int c = n0 + wn * 32 + ni * 8 + 2 * tg;
            const float b0 = bias[c], b1 = bias[c + 1];
            if (r0 < Mstore) {
                float2 v0 = make_float2(acc[mi][ni][0] + b0, acc[mi][ni][1] + b1);
                *reinterpret_cast<float2*>(&C[(size_t)r0 * N + c]) = v0;
            }
            if (r1 < Mstore) {
                float2 v1 = make_float2(acc[mi][ni][2] + b0, acc[mi][ni][3] + b1);
                *reinterpret_cast<float2*>(&C[(size_t)r1 * N + c]) = v1;
            }
        }
    }
}

// ============================================================================
// Exact fp32 GEMM:  C[4800 x N] = A[4800 x 256] * B[256 x N] + bias.
// Block tile 64x32, BK=32. grid = (N/32, 75). Used for Woff / Wattn (coords
// need full fp32 precision — tf32 noise amplifies through bilinear sampling).
// ============================================================================
__global__ __launch_bounds__(256, 4)
void fgemm64x32(const float* __restrict__ A, const float* __restrict__ Bm,
                const float* __restrict__ bias, float* __restrict__ C, int N) {
    __shared__ float As[64 * 36];
    __shared__ float Bs[32 * 36];

    const int tid = threadIdx.x;
    const int n0 = blockIdx.x * 32;
    const int m0 = blockIdx.y * 64;
    const int ty = tid >> 4, tx = tid & 15;

    const int arow = tid >> 3, acol = (tid & 7) * 4;

    float acc[4][2] = {};

    for (int kc = 0; kc < 256; kc += 32) {
        #pragma unroll
        for (int i = 0; i < 2; i++) {
            const float4 va = *reinterpret_cast<const float4*>(
                A + (size_t)(m0 + arow + i * 32) * 256 + kc + acol);
            *reinterpret_cast<float4*>(&As[(arow + i * 32) * 36 + acol]) = va;
        }
        {
            const float4 vb = *reinterpret_cast<const float4*>(
                Bm + (size_t)(kc + arow) * N + n0 + acol);
            *reinterpret_cast<float4*>(&Bs[arow * 36 + acol]) = vb;
        }
        __syncthreads();

        #pragma unroll
        for (int kk = 0; kk < 32; kk++) {
            float a0 = As[(ty * 4 + 0) * 36 + kk];
            float a1 = As[(ty * 4 + 1) * 36 + kk];
            float a2 = As[(ty * 4 + 2) * 36 + kk];
            float a3 = As[(ty * 4 + 3) * 36 + kk];
            float2 bv = *reinterpret_cast<const float2*>(&Bs[kk * 36 + tx * 2]);
            acc[0][0] += a0 * bv.x;  acc[0][1] += a0 * bv.y;
            acc[1][0] += a1 * bv.x;  acc[1][1] += a1 * bv.y;
            acc[2][0] += a2 * bv.x;  acc[2][1] += a2 * bv.y;
            acc[3][0] += a3 * bv.x;  acc[3][1] += a3 * bv.y;
        }
        __syncthreads();
    }

    const float b0 = bias[n0 + tx * 2], b1 = bias[n0 + tx * 2 + 1];
    #pragma unroll
    for (int i = 0; i < 4; i++) {
        float2 v = make_float2(acc[i][0] + b0, acc[i][1] + b1);
        *reinterpret_cast<float2*>(&C[(size_t)(m0 + ty * 4 + i) * N + n0 + tx * 2]) = v;
    }
}

// ============================================================================
// Deformable sampling: one warp per (b,q,h); lane = head dim (HD=32).
// Lanes 0..11 own one (level,point): softmax over 12 via warp butterfly,
// clipped pixel coords; broadcast via shfl; 4 guarded coalesced 128B gathers
// per point from g_v; weighted accumulate -> g_tmp[bq][h*32+lane].
// ============================================================================
__global__ __launch_bounds__(256)
void sample_kernel(const float* __restrict__ off, const float* __restrict__ attn,
                   const float* __restrict__ rp, const float* __restrict__ v,
                   float* __restrict__ tmp) {
    const int bq   = blockIdx.x;
    const int h    = threadIdx.x >> 5;
    const int lane = threadIdx.x & 31;
    const int b    = bq / Q_;

    const float refx = rp[bq * 4 + 0];
    const float refy = rp[bq * 4 + 1];

    float logit = -1e30f, px = 0.f, py = 0.f;
    if (lane < 12) {
        logit = attn[bq * 96 + h * 12 + lane];
        const float ox = off[bq * 192 + h * 24 + lane * 2 + 0];
        const float oy = off[bq * 192 + h * 24 + lane * 2 + 1];
        const int lvl = lane >> 2;
        const float Wf = (lvl == 0) ? 80.f : ((lvl == 1) ? 40.f : 20.f);
        const float ptsx = fminf(fmaxf(refx + ox, 0.f), 1.f);
        const float ptsy = fminf(fmaxf(refy + oy, 0.f), 1.f);
        px = ptsx * Wf - 0.5f;
        py = ptsy * Wf - 0.5f;
    }
    // softmax over the 12 valid lanes
    float mx = logit;
    #pragma unroll
    for (int s = 16; s > 0; s >>= 1) mx = fmaxf(mx, __shfl_xor_sync(0xffffffffu, mx, s));
    float e = (lane < 12) ? expf(logit - mx) : 0.f;
    float ssum = e;
    #pragma unroll
    for (int s = 16; s > 0; s >>= 1) ssum += __shfl_xor_sync(0xffffffffu, ssum, s);
    const float wgt = e / ssum;

    const float* vb = v + (size_t)b * LV * DMODEL + h * HD + lane;
    float acc = 0.f;

    #pragma unroll
    for (int j = 0; j < 12; j++) {
        const float pxj = __shfl_sync(0xffffffffu, px, j);
        const float pyj = __shfl_sync(0xffffffffu, py, j);
        const float wj  = __shfl_sync(0xffffffffu, wgt, j);
        const int lvl   = j >> 2;
        const int W     = (lvl == 0) ? 80 : ((lvl == 1) ? 40 : 20);
        const int Hh    = W;
        const int start = (lvl == 0) ? 0 : ((lvl == 1) ? 6400 : 8000);

        const float x0f = floorf(pxj), y0f = floorf(pyj);
        const float fx = pxj - x0f, fy = pyj - y0f;
        const int x0 = (int)x0f, y0 = (int)y0f;
        const float w00 = (1.f - fx) * (1.f - fy);
        const float w10 = fx * (1.f - fy);
        const float w01 = (1.f - fx) * fy;
        const float w11 = fx * fy;

        if ((unsigned)x0 < (unsigned)W && (unsigned)y0 < (unsigned)Hh)
            acc += wj * w00 * vb[(size_t)(start + y0 * W + x0) * DMODEL];
        if ((unsigned)(x0 + 1) < (unsigned)W && (unsigned)y0 < (unsigned)Hh)
            acc += wj * w10 * vb[(size_t)(start + y0 * W + x0 + 1) * DMODEL];
        if ((unsigned)x0 < (unsigned)W && (unsigned)(y0 + 1) < (unsigned)Hh)
            acc += wj * w01 * vb[(size_t)(start + (y0 + 1) * W + x0) * DMODEL];
        if ((unsigned)(x0 + 1) < (unsigned)W && (unsigned)(y0 + 1) < (unsigned)Hh)
            acc += wj * w11 * vb[(size_t)(start + (y0 + 1) * W + x0 + 1) * DMODEL];
    }

    tmp[(size_t)bq * DMODEL + h * HD + lane] = acc;
}

// ============================================================================
extern "C" void kernel_launch(void* const* d_in, const int* in_sizes, int n_in,
                              void* d_out, int out_size) {
    const float* query = (const float*)d_in[0];
    const float* rp    = (const float*)d_in[1];
    const float* value = (const float*)d_in[2];
    const float* Wv    = (const float*)d_in[3];
    const float* bv    = (const float*)d_in[4];
    const float* Woff  = (const float*)d_in[5];
    const float* boff  = (const float*)d_in[6];
    const float* Wattn = (const float*)d_in[7];
    const float* battn = (const float*)d_in[8];
    const float* Wout  = (const float*)d_in[9];
    const float* bout  = (const float*)d_in[10];
    float* out = (float*)d_out;

    float *pv, *poff, *pattn, *ptmp;
    cudaGetSymbolAddress((void**)&pv,    g_v);
    cudaGetSymbolAddress((void**)&poff,  g_off);
    cudaGetSymbolAddress((void**)&pattn, g_attn);
    cudaGetSymbolAddress((void**)&ptmp,  g_tmp);

    // 1) v = value @ Wv + bv   (tf32 tensor cores)
    gemm_tf32<<<dim3(2, MV / 128), 256>>>(value, Wv, bv, pv, MV, 256);
    // 2) offsets = query @ Woff + boff   (exact fp32 — coordinate precision)
    fgemm64x32<<<dim3(6, BQ / 64), 256>>>(query, Woff, boff, poff, 192);
    // 3) attn logits = query @ Wattn + battn   (exact fp32)
    fgemm64x32<<<dim3(3, BQ / 64), 256>>>(query, Wattn, battn, pattn, 96);
    // 4) softmax + deformable bilinear sampling -> g_tmp
    sample_kernel<<<BQ, 256>>>(poff, pattn, rp, pv, ptmp);
    // 5) out = tmp @ Wout + bout   (tf32, rows padded to 4864, stores guarded)
    gemm_tf32<<<dim3(2, MT_PAD / 128), 256>>>(ptmp, Wout, bout, out, BQ, 256);
}

// round 3
// speedup vs baseline: 1.3043x; 1.3043x over previous
#include <cuda_runtime.h>
#include <cuda_fp16.h>
#include <cstdint>

// ---------------- problem constants ----------------
#define B_      16
#define Q_      300
#define DMODEL  256
#define NHEADS  8
#define HD      32
#define LV      8400          // 80*80 + 40*40 + 20*20
#define BQ      (B_*Q_)       // 4800
#define MV      (B_*LV)       // 134400 rows of value
#define MT_PAD  4864          // 38*128

// ---------------- scratch (device globals; zero-initialized) ----------------
__device__ float g_v[MV * DMODEL];
__device__ float g_off[BQ * 192];
__device__ float g_attn[BQ * 96];
__device__ float g_tmp[MT_PAD * DMODEL];   // rows >= 4800 stay 0 forever

// ---------------- helpers ----------------
__device__ __forceinline__ uint32_t smem_u32(const void* p) {
    uint32_t a;
    asm("{ .reg .u64 t; cvta.to.shared.u64 t, %1; cvt.u32.u64 %0, t; }" : "=r"(a) : "l"(p));
    return a;
}

__device__ __forceinline__ void ldsm_x4(uint32_t* r, uint32_t addr) {
    asm volatile("ldmatrix.sync.aligned.m8n8.x4.shared.b16 {%0,%1,%2,%3}, [%4];"
                 : "=r"(r[0]), "=r"(r[1]), "=r"(r[2]), "=r"(r[3]) : "r"(addr));
}
__device__ __forceinline__ void ldsm_x4_t(uint32_t* r, uint32_t addr) {
    asm volatile("ldmatrix.sync.aligned.m8n8.x4.trans.shared.b16 {%0,%1,%2,%3}, [%4];"
                 : "=r"(r[0]), "=r"(r[1]), "=r"(r[2]), "=r"(r[3]) : "r"(addr));
}
__device__ __forceinline__ void mma16(float* c, const uint32_t* a, const uint32_t* b) {
    asm volatile(
        "mma.sync.aligned.m16n8k16.row.col.f32.f16.f16.f32 "
        "{%0,%1,%2,%3}, {%4,%5,%6,%7}, {%8,%9}, {%0,%1,%2,%3};\n"
        : "+f"(c[0]), "+f"(c[1]), "+f"(c[2]), "+f"(c[3])
        : "r"(a[0]), "r"(a[1]), "r"(a[2]), "r"(a[3]), "r"(b[0]), "r"(b[1]));
}
__device__ __forceinline__ uint32_t packh2(float x, float y) {
    __half2 h = __floats2half2_rn(x, y);
    return *reinterpret_cast<uint32_t*>(&h);
}

// ---------------- fp16 GEMM geometry ----------------
#define BK       32
#define ASTR     40    // halves per A row (pad: conflict-free ldmatrix phases)
#define BSTR     264   // halves per B row (256 + 8 pad)
#define A_HALVES (128 * ASTR)          // 5120
#define B_HALVES (32 * BSTR)           // 8448
#define SM_A0    0
#define SM_A1    (A_HALVES)
#define SM_B0    (2 * A_HALVES)
#define SM_B1    (2 * A_HALVES + B_HALVES)
#define SM_TOT_H (2 * A_HALVES + 2 * B_HALVES)       // 27136 halves
#define SM_TOT_B (SM_TOT_H * 2)                      // 54272 bytes

// ============================================================================
// fp16 tensor-core GEMM: C[M x 256] = A[M x 256] @ W[256 x 256] + bias.
// Block = 128 rows x 256 cols (full N). 8 warps as 2(m) x 4(n), warp 64x64.
// A fragments via ldmatrix, B via ldmatrix.trans. Double-buffered smem with
// register-staged prefetch. Stores guarded at Mstore (A rows must be readable
// to gridDim.x*128).
// ============================================================================
__global__ void __launch_bounds__(256, 1)
gemm_fp16(const float* __restrict__ A, const float* __restrict__ W,
          const float* __restrict__ bias, float* __restrict__ C, int Mstore) {
    extern __shared__ __half sh[];
    const uint32_t sb = smem_u32(sh);
    const int tid = threadIdx.x, warp = tid >> 5, lane = tid & 31;
    const int wm = warp >> 2, wn = warp & 3;         // 2 x 4 warp grid
    const int g = lane >> 2, tg = lane & 3;
    const int m0 = blockIdx.x * 128;

    // ---- fill assignments ----
    const int arow = tid >> 1, ac0 = (tid & 1) * 16;     // A: 4 float4 / thread
    const int brow = tid >> 3, bc0 = (tid & 7) * 4;      // B: 8 float4 / thread

    float acc[4][8][4];
    #pragma unroll
    for (int i = 0; i < 4; i++)
        #pragma unroll
        for (int j = 0; j < 8; j++)
            #pragma unroll
            for (int k = 0; k < 4; k++) acc[i][j][k] = 0.f;

    // ---- prologue: fill stage 0 (kc = 0) ----
    {
        const float* ap = A + (size_t)(m0 + arow) * 256 + ac0;
        #pragma unroll
        for (int i = 0; i < 4; i++) {
            float4 v = *reinterpret_cast<const float4*>(ap + 4 * i);
            uint2 u = make_uint2(packh2(v.x, v.y), packh2(v.z, v.w));
            *reinterpret_cast<uint2*>(&sh[SM_A0 + arow * ASTR + ac0 + 4 * i]) = u;
        }
        const float* wp = W + (size_t)brow * 256 + bc0;
        #pragma unroll
        for (int i = 0; i < 8; i++) {
            float4 v = *reinterpret_cast<const float4*>(wp + 32 * i);
            uint2 u = make_uint2(packh2(v.x, v.y), packh2(v.z, v.w));
            *reinterpret_cast<uint2*>(&sh[SM_B0 + brow * BSTR + bc0 + 32 * i]) = u;
        }
    }
    __syncthreads();

    // ldmatrix lane address components
    const uint32_t a_lrow = (uint32_t)(lane & 15);
    const uint32_t a_kadd = (uint32_t)(lane >> 4) * 8;

    #pragma unroll
    for (int c = 0; c < 8; c++) {
        const int cur = c & 1;
        float4 ra[4], rb[8];
        if (c < 7) {
            const int kc = (c + 1) * BK;
            const float* ap = A + (size_t)(m0 + arow) * 256 + kc + ac0;
            #pragma unroll
            for (int i = 0; i < 4; i++)
                ra[i] = *reinterpret_cast<const float4*>(ap + 4 * i);
            const float* wp = W + (size_t)(kc + brow) * 256 + bc0;
            #pragma unroll
            for (int i = 0; i < 8; i++)
                rb[i] = *reinterpret_cast<const float4*>(wp + 32 * i);
        }

        // ---- compute current stage ----
        const uint32_t aB = sb + (cur ? SM_A1 : SM_A0) * 2;
        const uint32_t bB = sb + (cur ? SM_B1 : SM_B0) * 2;
        #pragma unroll
        for (int k16 = 0; k16 < 2; k16++) {
            uint32_t af[4][4], bf[8][2];
            #pragma unroll
            for (int mi = 0; mi < 4; mi++) {
                uint32_t addr = aB + ((wm * 64 + mi * 16 + a_lrow) * ASTR
                                      + k16 * 16 + a_kadd) * 2;
                ldsm_x4(af[mi], addr);
            }
            #pragma unroll
            for (int nq = 0; nq < 4; nq++) {
                uint32_t r[4];
                uint32_t addr = bB + ((k16 * 16 + a_lrow) * BSTR
                                      + wn * 64 + nq * 16 + a_kadd) * 2;
                ldsm_x4_t(r, addr);
                bf[2 * nq][0] = r[0]; bf[2 * nq][1] = r[1];
                bf[2 * nq + 1][0] = r[2]; bf[2 * nq + 1][1] = r[3];
            }
            #pragma unroll
            for (int mi = 0; mi < 4; mi++)
                #pragma unroll
                for (int ni = 0; ni < 8; ni++)
                    mma16(acc[mi][ni], af[mi], bf[ni]);
        }

        if (c < 7) {
            const int nxt = (c + 1) & 1;
            __half* dA = &sh[(nxt ? SM_A1 : SM_A0)];
            __half* dB = &sh[(nxt ? SM_B1 : SM_B0)];
            #pragma unroll
            for (int i = 0; i < 4; i++) {
                uint2 u = make_uint2(packh2(ra[i].x, ra[i].y), packh2(ra[i].z, ra[i].w));
                *reinterpret_cast<uint2*>(&dA[arow * ASTR + ac0 + 4 * i]) = u;
            }
            #pragma unroll
            for (int i = 0; i < 8; i++) {
                uint2 u = make_uint2(packh2(rb[i].x, rb[i].y), packh2(rb[i].z, rb[i].w));
                *reinterpret_cast<uint2*>(&dB[brow * BSTR + bc0 + 32 * i]) = u;
            }
            __syncthreads();
        }
    }

    // ---- epilogue: + bias, guarded float2 stores ----
    #pragma unroll
    for (int mi = 0; mi < 4; mi++) {
        const int r0 = m0 + wm * 64 + mi * 16 + g;
        const int r1 = r0 + 8;
        #pragma unroll
        for (int ni = 0; ni < 8; ni++) {
            const int cc = wn * 64 + ni * 8 + 2 * tg;
            const float b0 = bias[cc], b1 = bias[cc + 1];
            if (r0 < Mstore)
                *reinterpret_cast<float2*>(&C[(size_t)r0 * 256 + cc]) =
                    make_float2(acc[mi][ni][0] + b0, acc[mi][ni][1] + b1);
            if (r1 < Mstore)
                *reinterpret_cast<float2*>(&C[(size_t)r1 * 256 + cc]) =
                    make_float2(acc[mi][ni][2] + b0, acc[mi][ni][3] + b1);
        }
    }
}

// ============================================================================
// Exact fp32 GEMM (coords need full precision): C[4800 x N] = A @ B + bias.
// ============================================================================
__global__ __launch_bounds__(256, 4)
void fgemm64x32(const float* __restrict__ A, const float* __restrict__ Bm,
                const float* __restrict__ bias, float* __restrict__ C, int N) {
    __shared__ float As[64 * 36];
    __shared__ float Bs[32 * 36];
    const int tid = threadIdx.x;
    const int n0 = blockIdx.x * 32;
    const int m0 = blockIdx.y * 64;
    const int ty = tid >> 4, tx = tid & 15;
    const int arow = tid >> 3, acol = (tid & 7) * 4;
    float acc[4][2] = {};
    for (int kc = 0; kc < 256; kc += 32) {
        #pragma unroll
        for (int i = 0; i < 2; i++) {
            const float4 va = *reinterpret_cast<const float4*>(
                A + (size_t)(m0 + arow + i * 32) * 256 + kc + acol);
            *reinterpret_cast<float4*>(&As[(arow + i * 32) * 36 + acol]) = va;
        }
        {
            const float4 vb = *reinterpret_cast<const float4*>(
                Bm + (size_t)(kc + arow) * N + n0 + acol);
            *reinterpret_cast<float4*>(&Bs[arow * 36 + acol]) = vb;
        }
        __syncthreads();
        #pragma unroll
        for (int kk = 0; kk < 32; kk++) {
            float a0 = As[(ty * 4 + 0) * 36 + kk];
            float a1 = As[(ty * 4 + 1) * 36 + kk];
            float a2 = As[(ty * 4 + 2) * 36 + kk];
            float a3 = As[(ty * 4 + 3) * 36 + kk];
            float2 bv = *reinterpret_cast<const float2*>(&Bs[kk * 36 + tx * 2]);
            acc[0][0] += a0 * bv.x;  acc[0][1] += a0 * bv.y;
            acc[1][0] += a1 * bv.x;  acc[1][1] += a1 * bv.y;
            acc[2][0] += a2 * bv.x;  acc[2][1] += a2 * bv.y;
            acc[3][0] += a3 * bv.x;  acc[3][1] += a3 * bv.y;
        }
        __syncthreads();
    }
    const float b0 = bias[n0 + tx * 2], b1 = bias[n0 + tx * 2 + 1];
    #pragma unroll
    for (int i = 0; i < 4; i++) {
        float2 v = make_float2(acc[i][0] + b0, acc[i][1] + b1);
        *reinterpret_cast<float2*>(&C[(size_t)(m0 + ty * 4 + i) * N + n0 + tx * 2]) = v;
    }
}

// ============================================================================
// Deformable sampling (unchanged)
// ============================================================================
__global__ __launch_bounds__(256)
void sample_kernel(const float* __restrict__ off, const float* __restrict__ attn,
                   const float* __restrict__ rp, const float* __restrict__ v,
                   float* __restrict__ tmp) {
    const int bq   = blockIdx.x;
    const int h    = threadIdx.x >> 5;
    const int lane = threadIdx.x & 31;
    const int b    = bq / Q_;

    const float refx = rp[bq * 4 + 0];
    const float refy = rp[bq * 4 + 1];

    float logit = -1e30f, px = 0.f, py = 0.f;
    if (lane < 12) {
        logit = attn[bq * 96 + h * 12 + lane];
        const float ox = off[bq * 192 + h * 24 + lane * 2 + 0];
        const float oy = off[bq * 192 + h * 24 + lane * 2 + 1];
        const int lvl = lane >> 2;
        const float Wf = (lvl == 0) ? 80.f : ((lvl == 1) ? 40.f : 20.f);
        const float ptsx = fminf(fmaxf(refx + ox, 0.f), 1.f);
        const float ptsy = fminf(fmaxf(refy + oy, 0.f), 1.f);
        px = ptsx * Wf - 0.5f;
        py = ptsy * Wf - 0.5f;
    }
    float mx = logit;
    #pragma unroll
    for (int s = 16; s > 0; s >>= 1) mx = fmaxf(mx, __shfl_xor_sync(0xffffffffu, mx, s));
    float e = (lane < 12) ? expf(logit - mx) : 0.f;
    float ssum = e;
    #pragma unroll
    for (int s = 16; s > 0; s >>= 1) ssum += __shfl_xor_sync(0xffffffffu, ssum, s);
    const float wgt = e / ssum;

    const float* vb = v + (size_t)b * LV * DMODEL + h * HD + lane;
    float acc = 0.f;

    #pragma unroll
    for (int j = 0; j < 12; j++) {
        const float pxj = __shfl_sync(0xffffffffu, px, j);
        const float pyj = __shfl_sync(0xffffffffu, py, j);
        const float wj  = __shfl_sync(0xffffffffu, wgt, j);
        const int lvl   = j >> 2;
        const int W     = (lvl == 0) ? 80 : ((lvl == 1) ? 40 : 20);
        const int Hh    = W;
        const int start = (lvl == 0) ? 0 : ((lvl == 1) ? 6400 : 8000);

        const float x0f = floorf(pxj), y0f = floorf(pyj);
        const float fx = pxj - x0f, fy = pyj - y0f;
        const int x0 = (int)x0f, y0 = (int)y0f;
        const float w00 = (1.f - fx) * (1.f - fy);
        const float w10 = fx * (1.f - fy);
        const float w01 = (1.f - fx) * fy;
        const float w11 = fx * fy;

        if ((unsigned)x0 < (unsigned)W && (unsigned)y0 < (unsigned)Hh)
            acc += wj * w00 * vb[(size_t)(start + y0 * W + x0) * DMODEL];
        if ((unsigned)(x0 + 1) < (unsigned)W && (unsigned)y0 < (unsigned)Hh)
            acc += wj * w10 * vb[(size_t)(start + y0 * W + x0 + 1) * DMODEL];
        if ((unsigned)x0 < (unsigned)W && (unsigned)(y0 + 1) < (unsigned)Hh)
            acc += wj * w01 * vb[(size_t)(start + (y0 + 1) * W + x0) * DMODEL];
        if ((unsigned)(x0 + 1) < (unsigned)W && (unsigned)(y0 + 1) < (unsigned)Hh)
            acc += wj * w11 * vb[(size_t)(start + (y0 + 1) * W + x0 + 1) * DMODEL];
    }

    tmp[(size_t)bq * DMODEL + h * HD + lane] = acc;
}

// ============================================================================
extern "C" void kernel_launch(void* const* d_in, const int* in_sizes, int n_in,
                              void* d_out, int out_size) {
    const float* query = (const float*)d_in[0];
    const float* rp    = (const float*)d_in[1];
    const float* value = (const float*)d_in[2];
    const float* Wv    = (const float*)d_in[3];
    const float* bv    = (const float*)d_in[4];
    const float* Woff  = (const float*)d_in[5];
    const float* boff  = (const float*)d_in[6];
    const float* Wattn = (const float*)d_in[7];
    const float* battn = (const float*)d_in[8];
    const float* Wout  = (const float*)d_in[9];
    const float* bout  = (const float*)d_in[10];
    float* out = (float*)d_out;

    float *pv, *poff, *pattn, *ptmp;
    cudaGetSymbolAddress((void**)&pv,    g_v);
    cudaGetSymbolAddress((void**)&poff,  g_off);
    cudaGetSymbolAddress((void**)&pattn, g_attn);
    cudaGetSymbolAddress((void**)&ptmp,  g_tmp);

    cudaFuncSetAttribute(gemm_fp16, cudaFuncAttributeMaxDynamicSharedMemorySize, SM_TOT_B);

    // 1) v = value @ Wv + bv   (fp16 tensor cores, ldmatrix + m16n8k16)
    gemm_fp16<<<MV / 128, 256, SM_TOT_B>>>(value, Wv, bv, pv, MV);
    // 2) offsets = query @ Woff + boff   (exact fp32 — coordinate precision)
    fgemm64x32<<<dim3(6, BQ / 64), 256>>>(query, Woff, boff, poff, 192);
    // 3) attn logits = query @ Wattn + battn   (exact fp32)
    fgemm64x32<<<dim3(3, BQ / 64), 256>>>(query, Wattn, battn, pattn, 96);
    // 4) softmax + deformable bilinear sampling -> g_tmp
    sample_kernel<<<BQ, 256>>>(poff, pattn, rp, pv, ptmp);
    // 5) out = tmp @ Wout + bout   (fp16 tensor cores, stores guarded)
    gemm_fp16<<<MT_PAD / 128, 256, SM_TOT_B>>>(ptmp, Wout, bout, out, BQ);
}